// round 14
// baseline (speedup 1.0000x reference)
#include <cuda_runtime.h>
#include <cuda_bf16.h>

// ObjectLoss: segment-normalized weighted MSE.
//   valid = reconstructable > 0
//   xi    = arctanh(beta)^2
//   mse   = sum_d (pred - track_params)^2
//   num[p] = sum_{i: pid_i==p, valid} mse_i * xi_i
//   den[p] = sum_{i: pid_i==p, valid} xi_i
//   out    = mean_{p=1..P-1} num[p]/den[p]
//
// Inputs (metadata order): beta [N] f32, pred [N*4] f32, particle_id [N] i32,
//                          track_params [N*4] f32, reconstructable [N] i32.
// Output: scalar f32.

#define P_SEGS 50000

__device__ float  g_num[P_SEGS];
__device__ float  g_den[P_SEGS];
__device__ double g_sum;

__global__ void init_kernel() {
    int i = blockIdx.x * blockDim.x + threadIdx.x;
    if (i < P_SEGS) {
        g_num[i] = 0.0f;
        g_den[i] = 0.0f;
    }
    if (i == 0) g_sum = 0.0;
}

__global__ __launch_bounds__(256) void accum_kernel(
    const float*  __restrict__ beta,
    const float4* __restrict__ pred,
    const int*    __restrict__ pid,
    const float4* __restrict__ tp,
    const int*    __restrict__ recon,
    int n)
{
    int i = blockIdx.x * blockDim.x + threadIdx.x;
    if (i >= n) return;

    int p = pid[i];
    int r = recon[i];
    // Route noise (pid==0) and non-reconstructable hits to nothing:
    // reference sends them to segment 0 which is dropped from the mean.
    if (r <= 0 || p == 0) return;

    float b  = beta[i];
    float4 q = pred[i];
    float4 t = tp[i];

    float a  = atanhf(b);
    float xi = a * a;

    float dx = q.x - t.x;
    float dy = q.y - t.y;
    float dz = q.z - t.z;
    float dw = q.w - t.w;
    float mse = dx * dx + dy * dy + dz * dz + dw * dw;

    atomicAdd(&g_num[p], mse * xi);
    atomicAdd(&g_den[p], xi);
}

__global__ __launch_bounds__(256) void reduce_kernel() {
    int i = blockIdx.x * blockDim.x + threadIdx.x;
    int p = i + 1;  // skip segment 0
    double v = 0.0;
    if (p < P_SEGS) {
        // Reference divides in f32; do the ratio on the f32 accumulators
        // (promoted to double only for the big sum, which is where
        //  catastrophic rounding could otherwise appear).
        v = (double)(g_num[p] / g_den[p]);
    }

    // warp reduce
    #pragma unroll
    for (int off = 16; off > 0; off >>= 1)
        v += __shfl_down_sync(0xffffffffu, v, off);

    __shared__ double warp_sums[8];
    int lane = threadIdx.x & 31;
    int wid  = threadIdx.x >> 5;
    if (lane == 0) warp_sums[wid] = v;
    __syncthreads();

    if (wid == 0) {
        v = (lane < (int)(blockDim.x >> 5)) ? warp_sums[lane] : 0.0;
        #pragma unroll
        for (int off = 4; off > 0; off >>= 1)
            v += __shfl_down_sync(0xffffffffu, v, off);
        if (lane == 0) atomicAdd(&g_sum, v);
    }
}

__global__ void finalize_kernel(float* out) {
    *out = (float)(g_sum / (double)(P_SEGS - 1));
}

extern "C" void kernel_launch(void* const* d_in, const int* in_sizes, int n_in,
                              void* d_out, int out_size) {
    const float* beta  = (const float*)d_in[0];
    const float* pred  = (const float*)d_in[1];
    const int*   pid   = (const int*)d_in[2];
    const float* tp    = (const float*)d_in[3];
    const int*   recon = (const int*)d_in[4];
    int n = in_sizes[0];

    init_kernel<<<(P_SEGS + 255) / 256, 256>>>();
    accum_kernel<<<(n + 255) / 256, 256>>>(
        beta, (const float4*)pred, pid, (const float4*)tp, recon, n);
    reduce_kernel<<<(P_SEGS - 1 + 255) / 256, 256>>>();
    finalize_kernel<<<1, 1>>>((float*)d_out);
}